// round 3
// baseline (speedup 1.0000x reference)
#include <cuda_runtime.h>
#include <cuda_bf16.h>
#include <math.h>

// Problem constants
#define BATCH 64
#define TT    1024
#define DIN   64
#define HID   128
#define G3    384   // 3*HID
#define D2    256   // 2*HID
#define MROWS (BATCH*TT)   // 65536

typedef unsigned long long ull;

// ---------------- f32x2 packed helpers (sm_103a FFMA2) ----------------------
__device__ __forceinline__ ull fma2(ull a, ull b, ull c) {
    ull d;
    asm("fma.rn.f32x2 %0, %1, %2, %3;" : "=l"(d) : "l"(a), "l"(b), "l"(c));
    return d;
}
__device__ __forceinline__ ull pack2(float lo, float hi) {
    ull d;
    asm("mov.b64 %0, {%1, %2};" : "=l"(d) : "f"(lo), "f"(hi));
    return d;
}
__device__ __forceinline__ float2 unpack2(ull v) {
    float2 r;
    asm("mov.b64 {%0, %1}, %2;" : "=f"(r.x), "=f"(r.y) : "l"(v));
    return r;
}
__device__ __forceinline__ float sigm(float x) {
    return 1.f / (1.f + __expf(-x));
}
__device__ __forceinline__ float ftanh(float x) {
    return __fmaf_rn(2.f, 1.f / (1.f + __expf(-2.f * x)), -1.f);
}

// ---------------- scratch (device globals; no allocation allowed) ----------
__device__ float g_xW[2][MROWS][G3];   // per-dir input projections (reused L0/L1)
__device__ float g_z0[MROWS][D2];      // layer-0 output [b*T+t][256]
__device__ float g_z1[MROWS][D2];      // layer-1 output

// ---------------- input projection GEMM: C = A @ W^T + bias ----------------
__global__ __launch_bounds__(256)
void proj_gemm_kernel(const float* __restrict__ A0,
                      const float* __restrict__ Wf, const float* __restrict__ Wb,
                      const float* __restrict__ bf, const float* __restrict__ bb,
                      int K, int layer)
{
    constexpr int BM = 128, BN = 64, BK = 16;
    __shared__ __align__(16) float As[BK][BM + 4];
    __shared__ __align__(16) float Ws[BK][BN + 4];

    const int dir = blockIdx.z;
    const float* __restrict__ A    = layer ? (const float*)g_z0 : A0;
    const float* __restrict__ Wp   = dir ? Wb : Wf;
    const float* __restrict__ bias = dir ? bb : bf;

    const int m0 = blockIdx.x * BM;
    const int n0 = blockIdx.y * BN;

    const int tid  = threadIdx.x;
    const int arow = tid >> 2;           // 0..63
    const int kq   = (tid & 3) * 4;      // 0,4,8,12
    const int tx   = tid & 15;           // N micro (4)
    const int ty   = tid >> 4;           // M micro (8 rows = 4 f32x2 pairs)

    ull acc2[4][4];
    #pragma unroll
    for (int i = 0; i < 4; ++i)
        #pragma unroll
        for (int j = 0; j < 4; ++j) acc2[i][j] = 0ull;

    for (int k0 = 0; k0 < K; k0 += BK) {
        {
            const float* p = A + (size_t)(m0 + arow) * K + k0 + kq;
            float4 v0 = *(const float4*)p;
            float4 v1 = *(const float4*)(p + (size_t)64 * K);
            As[kq + 0][arow] = v0.x; As[kq + 1][arow] = v0.y;
            As[kq + 2][arow] = v0.z; As[kq + 3][arow] = v0.w;
            As[kq + 0][arow + 64] = v1.x; As[kq + 1][arow + 64] = v1.y;
            As[kq + 2][arow + 64] = v1.z; As[kq + 3][arow + 64] = v1.w;
        }
        {
            const float* p = Wp + (size_t)(n0 + arow) * K + k0 + kq;
            float4 v = *(const float4*)p;
            Ws[kq + 0][arow] = v.x; Ws[kq + 1][arow] = v.y;
            Ws[kq + 2][arow] = v.z; Ws[kq + 3][arow] = v.w;
        }
        __syncthreads();

        #pragma unroll
        for (int kk = 0; kk < BK; ++kk) {
            ulonglong2 a01 = *(const ulonglong2*)&As[kk][ty * 8];
            ulonglong2 a23 = *(const ulonglong2*)&As[kk][ty * 8 + 4];
            float4 w4 = *(const float4*)&Ws[kk][tx * 4];
            ull am[4] = {a01.x, a01.y, a23.x, a23.y};
            ull wp[4] = {pack2(w4.x, w4.x), pack2(w4.y, w4.y),
                         pack2(w4.z, w4.z), pack2(w4.w, w4.w)};
            #pragma unroll
            for (int i = 0; i < 4; ++i)
                #pragma unroll
                for (int j = 0; j < 4; ++j)
                    acc2[i][j] = fma2(am[i], wp[j], acc2[i][j]);
        }
        __syncthreads();
    }

    float* Cout = &g_xW[dir][0][0];
    float4 b4 = *(const float4*)(bias + n0 + tx * 4);
    float* Crow = Cout + (size_t)(m0 + ty * 8) * G3 + n0 + tx * 4;
    #pragma unroll
    for (int i = 0; i < 4; ++i) {
        float2 c0 = unpack2(acc2[i][0]);
        float2 c1 = unpack2(acc2[i][1]);
        float2 c2 = unpack2(acc2[i][2]);
        float2 c3 = unpack2(acc2[i][3]);
        float4 lo = {c0.x + b4.x, c1.x + b4.y, c2.x + b4.z, c3.x + b4.w};
        float4 hi = {c0.y + b4.x, c1.y + b4.y, c2.y + b4.z, c3.y + b4.w};
        *(float4*)(Crow + (size_t)(2 * i)     * G3) = lo;
        *(float4*)(Crow + (size_t)(2 * i + 1) * G3) = hi;
    }
}

// ---------------- GRU recurrence -------------------------------------------
// one block per (batch, dir); 13 warps. Warp w, lane l<30:
//   output o = w*10 + l%10, gate g = l/10 (0=r,1=z,2=n), row = g*128+o.
// All 3 gates of an output live in one warp -> gh exchanged via shfl,
// gate math inline, single barrier per step, h double-buffered in smem.
#define SCAN_NT 416
__global__ __launch_bounds__(SCAN_NT, 1)
void gru_scan_kernel(const float* __restrict__ whh_f, const float* __restrict__ whh_b,
                     const float* __restrict__ bhh_f, const float* __restrict__ bhh_b,
                     int layer)
{
    const int b   = blockIdx.x >> 1;
    const int dir = blockIdx.x & 1;
    const int tid = threadIdx.x;
    const int w   = tid >> 5;
    const int l   = tid & 31;

    const int g_raw = l / 10;                  // 0,1,2 (3 for lanes 30,31)
    const int g     = (g_raw < 3) ? g_raw : 0;
    const int o     = w * 10 + (l - g_raw * 10 < 10 ? (l % 10) : 0); // l%10 ok for l<30
    const int oc    = (o < HID) ? o : (HID - 1);
    const int row   = g * HID + oc;
    const bool is_gate = (g_raw == 0) && (o < HID);

    const float* __restrict__ whh = dir ? whh_b : whh_f;
    const float* __restrict__ bhh = dir ? bhh_b : bhh_f;

    __shared__ __align__(16) float h_s[2][HID];

    // load Whh row into 64 packed f32x2 registers
    ull w2[64];
    #pragma unroll
    for (int i = 0; i < 64; i += 2) {
        ulonglong2 v = *(const ulonglong2*)(whh + (size_t)row * HID + 2 * i);
        w2[i] = v.x; w2[i + 1] = v.y;
    }
    const float bj = bhh[row];
    float hreg = 0.f;
    if (tid < HID) h_s[0][tid] = 0.f;

    const float* __restrict__ gi = &g_xW[dir][(size_t)b * TT][0];
    float* __restrict__ zout = (layer ? &g_z1[(size_t)b * TT][0]
                                      : &g_z0[(size_t)b * TT][0]) + dir * HID;
    __syncthreads();

    int p = 0;
    for (int t = 0; t < TT; ++t) {
        const int tt = dir ? (TT - 1 - t) : t;

        // gate lanes prefetch their 3 input-projection values
        float gi_r = 0.f, gi_z = 0.f, gi_n = 0.f;
        if (is_gate) {
            const float* gp = gi + (size_t)tt * G3 + o;
            gi_r = __ldg(gp);
            gi_z = __ldg(gp + HID);
            gi_n = __ldg(gp + 2 * HID);
        }

        // gh = Whh[row,:] . h  via packed FFMA2 (4 independent chains)
        ull a0 = pack2(bj, 0.f), a1 = 0ull, a2 = 0ull, a3 = 0ull;
        const ull* h2 = (const ull*)h_s[p];
        #pragma unroll
        for (int i = 0; i < 64; i += 4) {
            ulonglong2 hv0 = *(const ulonglong2*)(h2 + i);
            ulonglong2 hv1 = *(const ulonglong2*)(h2 + i + 2);
            a0 = fma2(w2[i],     hv0.x, a0);
            a1 = fma2(w2[i + 1], hv0.y, a1);
            a2 = fma2(w2[i + 2], hv1.x, a2);
            a3 = fma2(w2[i + 3], hv1.y, a3);
        }
        float2 s0 = unpack2(a0), s1 = unpack2(a1), s2 = unpack2(a2), s3 = unpack2(a3);
        float gh = ((s0.x + s0.y) + (s1.x + s1.y)) + ((s2.x + s2.y) + (s3.x + s3.y));

        // in-warp gate exchange: r-lane l gets z from lane l+10, n from l+20
        float gh_z = __shfl_sync(0xffffffffu, gh, l + 10);
        float gh_n = __shfl_sync(0xffffffffu, gh, l + 20);

        if (is_gate) {
            float r  = sigm(gi_r + gh);
            float zg = sigm(gi_z + gh_z);
            float n  = ftanh(gi_n + r * gh_n);
            hreg = (1.f - zg) * n + zg * hreg;
            h_s[p ^ 1][o] = hreg;
            zout[(size_t)tt * D2 + o] = hreg;
        }
        __syncthreads();
        p ^= 1;
    }
}

// ---------------- attention pooling + heads --------------------------------
__global__ __launch_bounds__(256)
void attn_head_kernel(const float* __restrict__ attn_w, const float* __restrict__ attn_b,
                      const float* __restrict__ motor_w, const float* __restrict__ motor_b,
                      const float* __restrict__ state_w, const float* __restrict__ state_b,
                      const int* __restrict__ motor_k, float* __restrict__ out)
{
    const int b = blockIdx.x;
    const int tid = threadIdx.x;       // 256 threads
    const int warp = tid >> 5, lane = tid & 31;

    __shared__ float sw[D2];
    __shared__ float sc[TT];
    __shared__ float red[256];
    __shared__ float pooled[D2];

    sw[tid] = attn_w[tid];
    __syncthreads();

    const float* __restrict__ zb = &g_z1[(size_t)b * TT][0];
    const float ab = attn_b[0];

    for (int t = warp; t < TT; t += 8) {
        const float* zt = zb + (size_t)t * D2;
        float s = 0.f;
        #pragma unroll
        for (int d = lane; d < D2; d += 32) s += zt[d] * sw[d];
        #pragma unroll
        for (int o = 16; o; o >>= 1) s += __shfl_xor_sync(0xffffffffu, s, o);
        if (lane == 0) sc[t] = s + ab;
    }
    __syncthreads();

    float m = -INFINITY;
    for (int t = tid; t < TT; t += 256) m = fmaxf(m, sc[t]);
    red[tid] = m; __syncthreads();
    for (int s = 128; s; s >>= 1) {
        if (tid < s) red[tid] = fmaxf(red[tid], red[tid + s]);
        __syncthreads();
    }
    m = red[0]; __syncthreads();

    float sum = 0.f;
    for (int t = tid; t < TT; t += 256) {
        float e = __expf(sc[t] - m);
        sc[t] = e;
        sum += e;
    }
    red[tid] = sum; __syncthreads();
    for (int s = 128; s; s >>= 1) {
        if (tid < s) red[tid] += red[tid + s];
        __syncthreads();
    }
    const float inv = 1.f / red[0];
    __syncthreads();

    float acc = 0.f;
    #pragma unroll 8
    for (int t = 0; t < TT; ++t) acc += sc[t] * zb[(size_t)t * D2 + tid];
    pooled[tid] = acc * inv;
    __syncthreads();

    if (warp < 7) {
        const float* wv;
        float bv;
        int mk = motor_k[b];
        if (warp < 5) { wv = motor_w + warp * D2;              bv = motor_b[warp]; }
        else          { int c = warp - 5;
                        wv = state_w + (size_t)(mk * 2 + c) * D2;
                        bv = state_b[mk * 2 + c]; }
        float s = 0.f;
        #pragma unroll
        for (int d = lane; d < D2; d += 32) s += pooled[d] * wv[d];
        #pragma unroll
        for (int o = 16; o; o >>= 1) s += __shfl_xor_sync(0xffffffffu, s, o);
        if (lane == 0) {
            if (warp < 5) out[b * 5 + warp] = s + bv;
            else          out[BATCH * 5 + b * 2 + (warp - 5)] = s + bv;
        }
    }
}

// ---------------- launch ----------------------------------------------------
extern "C" void kernel_launch(void* const* d_in, const int* in_sizes, int n_in,
                              void* d_out, int out_size)
{
    const float* x        = (const float*)d_in[0];
    const int*   motor_k  = (const int*)  d_in[1];
    const float* wih_l0f  = (const float*)d_in[2];
    const float* whh_l0f  = (const float*)d_in[3];
    const float* bih_l0f  = (const float*)d_in[4];
    const float* bhh_l0f  = (const float*)d_in[5];
    const float* wih_l0b  = (const float*)d_in[6];
    const float* whh_l0b  = (const float*)d_in[7];
    const float* bih_l0b  = (const float*)d_in[8];
    const float* bhh_l0b  = (const float*)d_in[9];
    const float* wih_l1f  = (const float*)d_in[10];
    const float* whh_l1f  = (const float*)d_in[11];
    const float* bih_l1f  = (const float*)d_in[12];
    const float* bhh_l1f  = (const float*)d_in[13];
    const float* wih_l1b  = (const float*)d_in[14];
    const float* whh_l1b  = (const float*)d_in[15];
    const float* bih_l1b  = (const float*)d_in[16];
    const float* bhh_l1b  = (const float*)d_in[17];
    const float* attn_w   = (const float*)d_in[18];
    const float* attn_b   = (const float*)d_in[19];
    const float* motor_w  = (const float*)d_in[20];
    const float* motor_b  = (const float*)d_in[21];
    const float* state_w  = (const float*)d_in[22];
    const float* state_b  = (const float*)d_in[23];
    float* out = (float*)d_out;

    dim3 gproj(MROWS / 128, G3 / 64, 2);

    // layer 0
    proj_gemm_kernel<<<gproj, 256>>>(x, wih_l0f, wih_l0b, bih_l0f, bih_l0b, DIN, 0);
    gru_scan_kernel<<<BATCH * 2, SCAN_NT>>>(whh_l0f, whh_l0b, bhh_l0f, bhh_l0b, 0);
    // layer 1
    proj_gemm_kernel<<<gproj, 256>>>(nullptr, wih_l1f, wih_l1b, bih_l1f, bih_l1b, D2, 1);
    gru_scan_kernel<<<BATCH * 2, SCAN_NT>>>(whh_l1f, whh_l1b, bhh_l1f, bhh_l1b, 1);
    // pooling + heads
    attn_head_kernel<<<BATCH, 256>>>(attn_w, attn_b, motor_w, motor_b,
                                     state_w, state_b, motor_k, out);
}

// round 4
// speedup vs baseline: 2.4682x; 2.4682x over previous
#include <cuda_runtime.h>
#include <cuda_bf16.h>
#include <math.h>

// Problem constants
#define BATCH 64
#define TT    1024
#define DIN   64
#define HID   128
#define G3    384   // 3*HID
#define D2    256   // 2*HID
#define MROWS (BATCH*TT)   // 65536

typedef unsigned long long ull;

// ---------------- f32x2 packed helpers (sm_103a FFMA2) ----------------------
__device__ __forceinline__ ull fma2(ull a, ull b, ull c) {
    ull d;
    asm("fma.rn.f32x2 %0, %1, %2, %3;" : "=l"(d) : "l"(a), "l"(b), "l"(c));
    return d;
}
__device__ __forceinline__ ull pack2(float lo, float hi) {
    ull d;
    asm("mov.b64 %0, {%1, %2};" : "=l"(d) : "f"(lo), "f"(hi));
    return d;
}
__device__ __forceinline__ float2 unpack2(ull v) {
    float2 r;
    asm("mov.b64 {%0, %1}, %2;" : "=f"(r.x), "=f"(r.y) : "l"(v));
    return r;
}
__device__ __forceinline__ float sigm(float x) {
    return 1.f / (1.f + __expf(-x));
}
__device__ __forceinline__ float ftanh(float x) {
    return __fmaf_rn(2.f, 1.f / (1.f + __expf(-2.f * x)), -1.f);
}

// ---------------- scratch (device globals; no allocation allowed) ----------
__device__ float g_xW[2][MROWS][G3];   // per-dir input projections (reused L0/L1)
__device__ float g_z0[MROWS][D2];      // layer-0 output [b*T+t][256]
__device__ float g_z1[MROWS][D2];      // layer-1 output

// ---------------- input projection GEMM: C = A @ W^T + bias ----------------
__global__ __launch_bounds__(256)
void proj_gemm_kernel(const float* __restrict__ A0,
                      const float* __restrict__ Wf, const float* __restrict__ Wb,
                      const float* __restrict__ bf, const float* __restrict__ bb,
                      int K, int layer)
{
    constexpr int BM = 128, BN = 64, BK = 16;
    __shared__ __align__(16) float As[BK][BM + 4];
    __shared__ __align__(16) float Ws[BK][BN + 4];

    const int dir = blockIdx.z;
    const float* __restrict__ A    = layer ? (const float*)g_z0 : A0;
    const float* __restrict__ Wp   = dir ? Wb : Wf;
    const float* __restrict__ bias = dir ? bb : bf;

    const int m0 = blockIdx.x * BM;
    const int n0 = blockIdx.y * BN;

    const int tid  = threadIdx.x;
    const int arow = tid >> 2;           // 0..63
    const int kq   = (tid & 3) * 4;      // 0,4,8,12
    const int tx   = tid & 15;           // N micro (4)
    const int ty   = tid >> 4;           // M micro (8 rows = 4 f32x2 pairs)

    ull acc2[4][4];
    #pragma unroll
    for (int i = 0; i < 4; ++i)
        #pragma unroll
        for (int j = 0; j < 4; ++j) acc2[i][j] = 0ull;

    for (int k0 = 0; k0 < K; k0 += BK) {
        {
            const float* p = A + (size_t)(m0 + arow) * K + k0 + kq;
            float4 v0 = *(const float4*)p;
            float4 v1 = *(const float4*)(p + (size_t)64 * K);
            As[kq + 0][arow] = v0.x; As[kq + 1][arow] = v0.y;
            As[kq + 2][arow] = v0.z; As[kq + 3][arow] = v0.w;
            As[kq + 0][arow + 64] = v1.x; As[kq + 1][arow + 64] = v1.y;
            As[kq + 2][arow + 64] = v1.z; As[kq + 3][arow + 64] = v1.w;
        }
        {
            const float* p = Wp + (size_t)(n0 + arow) * K + k0 + kq;
            float4 v = *(const float4*)p;
            Ws[kq + 0][arow] = v.x; Ws[kq + 1][arow] = v.y;
            Ws[kq + 2][arow] = v.z; Ws[kq + 3][arow] = v.w;
        }
        __syncthreads();

        #pragma unroll
        for (int kk = 0; kk < BK; ++kk) {
            ulonglong2 a01 = *(const ulonglong2*)&As[kk][ty * 8];
            ulonglong2 a23 = *(const ulonglong2*)&As[kk][ty * 8 + 4];
            float4 w4 = *(const float4*)&Ws[kk][tx * 4];
            ull am[4] = {a01.x, a01.y, a23.x, a23.y};
            ull wp[4] = {pack2(w4.x, w4.x), pack2(w4.y, w4.y),
                         pack2(w4.z, w4.z), pack2(w4.w, w4.w)};
            #pragma unroll
            for (int i = 0; i < 4; ++i)
                #pragma unroll
                for (int j = 0; j < 4; ++j)
                    acc2[i][j] = fma2(am[i], wp[j], acc2[i][j]);
        }
        __syncthreads();
    }

    float* Cout = &g_xW[dir][0][0];
    float4 b4 = *(const float4*)(bias + n0 + tx * 4);
    float* Crow = Cout + (size_t)(m0 + ty * 8) * G3 + n0 + tx * 4;
    #pragma unroll
    for (int i = 0; i < 4; ++i) {
        float2 c0 = unpack2(acc2[i][0]);
        float2 c1 = unpack2(acc2[i][1]);
        float2 c2 = unpack2(acc2[i][2]);
        float2 c3 = unpack2(acc2[i][3]);
        float4 lo = {c0.x + b4.x, c1.x + b4.y, c2.x + b4.z, c3.x + b4.w};
        float4 hi = {c0.y + b4.x, c1.y + b4.y, c2.y + b4.z, c3.y + b4.w};
        *(float4*)(Crow + (size_t)(2 * i)     * G3) = lo;
        *(float4*)(Crow + (size_t)(2 * i + 1) * G3) = hi;
    }
}

// ---------------- GRU recurrence -------------------------------------------
// one block per (batch, dir); 384 threads, Whh row-per-thread in registers.
// gi (input projection) stream is DRAM-resident: prefetch one step ahead so
// the ~600cyc miss latency is covered by a full step of work.
__global__ __launch_bounds__(384, 1)
void gru_scan_kernel(const float* __restrict__ whh_f, const float* __restrict__ whh_b,
                     const float* __restrict__ bhh_f, const float* __restrict__ bhh_b,
                     int layer)
{
    const int b   = blockIdx.x >> 1;
    const int dir = blockIdx.x & 1;
    const int j   = threadIdx.x;                 // 0..383

    const float* __restrict__ whh = dir ? whh_b : whh_f;
    const float* __restrict__ bhh = dir ? bhh_b : bhh_f;

    __shared__ __align__(16) float h_s[HID];
    __shared__ float gh_s[G3];

    // load Whh row j into 64 packed f32x2 registers
    ull w2[64];
    #pragma unroll
    for (int i = 0; i < 64; i += 2) {
        ulonglong2 v = *(const ulonglong2*)(whh + (size_t)j * HID + 2 * i);
        w2[i] = v.x; w2[i + 1] = v.y;
    }
    const float bj = bhh[j];
    float hreg = 0.f;
    if (j < HID) h_s[j] = 0.f;

    const float* __restrict__ gi = &g_xW[dir][(size_t)b * TT][0];
    float* __restrict__ zout = (layer ? &g_z1[(size_t)b * TT][0]
                                      : &g_z0[(size_t)b * TT][0]) + dir * HID;

    // preload gi for the first step (gate threads only)
    float gi_r = 0.f, gi_z = 0.f, gi_n = 0.f;
    if (j < HID) {
        const int t0 = dir ? (TT - 1) : 0;
        const float* gp = gi + (size_t)t0 * G3 + j;
        gi_r = __ldcs(gp);
        gi_z = __ldcs(gp + HID);
        gi_n = __ldcs(gp + 2 * HID);
    }
    __syncthreads();

    for (int t = 0; t < TT; ++t) {
        const int tt = dir ? (TT - 1 - t) : t;

        // prefetch NEXT step's gi (consumed ~1 full step later)
        float p_r = 0.f, p_z = 0.f, p_n = 0.f;
        if (j < HID && t + 1 < TT) {
            const int tn = dir ? (TT - 2 - t) : (t + 1);
            const float* gp = gi + (size_t)tn * G3 + j;
            p_r = __ldcs(gp);
            p_z = __ldcs(gp + HID);
            p_n = __ldcs(gp + 2 * HID);
        }

        // gh[j] = Whh[j,:] . h  via packed FFMA2 (2 chains, saves regs)
        ull a0 = pack2(bj, 0.f), a1 = 0ull;
        const ull* h2 = (const ull*)h_s;
        #pragma unroll
        for (int i = 0; i < 64; i += 2) {
            ulonglong2 hv = *(const ulonglong2*)(h2 + i);
            a0 = fma2(w2[i],     hv.x, a0);
            a1 = fma2(w2[i + 1], hv.y, a1);
        }
        float2 s0 = unpack2(a0), s1 = unpack2(a1);
        gh_s[j] = (s0.x + s0.y) + (s1.x + s1.y);
        __syncthreads();

        if (j < HID) {
            float r  = sigm(gi_r + gh_s[j]);
            float zg = sigm(gi_z + gh_s[HID + j]);
            float n  = ftanh(gi_n + r * gh_s[2 * HID + j]);
            hreg = (1.f - zg) * n + zg * hreg;
            h_s[j] = hreg;
            zout[(size_t)tt * D2 + j] = hreg;
        }
        gi_r = p_r; gi_z = p_z; gi_n = p_n;
        __syncthreads();
    }
}

// ---------------- attention pooling + heads --------------------------------
__global__ __launch_bounds__(256)
void attn_head_kernel(const float* __restrict__ attn_w, const float* __restrict__ attn_b,
                      const float* __restrict__ motor_w, const float* __restrict__ motor_b,
                      const float* __restrict__ state_w, const float* __restrict__ state_b,
                      const int* __restrict__ motor_k, float* __restrict__ out)
{
    const int b = blockIdx.x;
    const int tid = threadIdx.x;       // 256 threads
    const int warp = tid >> 5, lane = tid & 31;

    __shared__ float sw[D2];
    __shared__ float sc[TT];
    __shared__ float red[256];
    __shared__ float pooled[D2];

    sw[tid] = attn_w[tid];
    __syncthreads();

    const float* __restrict__ zb = &g_z1[(size_t)b * TT][0];
    const float ab = attn_b[0];

    for (int t = warp; t < TT; t += 8) {
        const float* zt = zb + (size_t)t * D2;
        float s = 0.f;
        #pragma unroll
        for (int d = lane; d < D2; d += 32) s += zt[d] * sw[d];
        #pragma unroll
        for (int o = 16; o; o >>= 1) s += __shfl_xor_sync(0xffffffffu, s, o);
        if (lane == 0) sc[t] = s + ab;
    }
    __syncthreads();

    float m = -INFINITY;
    for (int t = tid; t < TT; t += 256) m = fmaxf(m, sc[t]);
    red[tid] = m; __syncthreads();
    for (int s = 128; s; s >>= 1) {
        if (tid < s) red[tid] = fmaxf(red[tid], red[tid + s]);
        __syncthreads();
    }
    m = red[0]; __syncthreads();

    float sum = 0.f;
    for (int t = tid; t < TT; t += 256) {
        float e = __expf(sc[t] - m);
        sc[t] = e;
        sum += e;
    }
    red[tid] = sum; __syncthreads();
    for (int s = 128; s; s >>= 1) {
        if (tid < s) red[tid] += red[tid + s];
        __syncthreads();
    }
    const float inv = 1.f / red[0];
    __syncthreads();

    float acc = 0.f;
    #pragma unroll 8
    for (int t = 0; t < TT; ++t) acc += sc[t] * zb[(size_t)t * D2 + tid];
    pooled[tid] = acc * inv;
    __syncthreads();

    if (warp < 7) {
        const float* wv;
        float bv;
        int mk = motor_k[b];
        if (warp < 5) { wv = motor_w + warp * D2;              bv = motor_b[warp]; }
        else          { int c = warp - 5;
                        wv = state_w + (size_t)(mk * 2 + c) * D2;
                        bv = state_b[mk * 2 + c]; }
        float s = 0.f;
        #pragma unroll
        for (int d = lane; d < D2; d += 32) s += pooled[d] * wv[d];
        #pragma unroll
        for (int o = 16; o; o >>= 1) s += __shfl_xor_sync(0xffffffffu, s, o);
        if (lane == 0) {
            if (warp < 5) out[b * 5 + warp] = s + bv;
            else          out[BATCH * 5 + b * 2 + (warp - 5)] = s + bv;
        }
    }
}

// ---------------- launch ----------------------------------------------------
extern "C" void kernel_launch(void* const* d_in, const int* in_sizes, int n_in,
                              void* d_out, int out_size)
{
    const float* x        = (const float*)d_in[0];
    const int*   motor_k  = (const int*)  d_in[1];
    const float* wih_l0f  = (const float*)d_in[2];
    const float* whh_l0f  = (const float*)d_in[3];
    const float* bih_l0f  = (const float*)d_in[4];
    const float* bhh_l0f  = (const float*)d_in[5];
    const float* wih_l0b  = (const float*)d_in[6];
    const float* whh_l0b  = (const float*)d_in[7];
    const float* bih_l0b  = (const float*)d_in[8];
    const float* bhh_l0b  = (const float*)d_in[9];
    const float* wih_l1f  = (const float*)d_in[10];
    const float* whh_l1f  = (const float*)d_in[11];
    const float* bih_l1f  = (const float*)d_in[12];
    const float* bhh_l1f  = (const float*)d_in[13];
    const float* wih_l1b  = (const float*)d_in[14];
    const float* whh_l1b  = (const float*)d_in[15];
    const float* bih_l1b  = (const float*)d_in[16];
    const float* bhh_l1b  = (const float*)d_in[17];
    const float* attn_w   = (const float*)d_in[18];
    const float* attn_b   = (const float*)d_in[19];
    const float* motor_w  = (const float*)d_in[20];
    const float* motor_b  = (const float*)d_in[21];
    const float* state_w  = (const float*)d_in[22];
    const float* state_b  = (const float*)d_in[23];
    float* out = (float*)d_out;

    dim3 gproj(MROWS / 128, G3 / 64, 2);

    // layer 0
    proj_gemm_kernel<<<gproj, 256>>>(x, wih_l0f, wih_l0b, bih_l0f, bih_l0b, DIN, 0);
    gru_scan_kernel<<<BATCH * 2, 384>>>(whh_l0f, whh_l0b, bhh_l0f, bhh_l0b, 0);
    // layer 1
    proj_gemm_kernel<<<gproj, 256>>>(nullptr, wih_l1f, wih_l1b, bih_l1f, bih_l1b, D2, 1);
    gru_scan_kernel<<<BATCH * 2, 384>>>(whh_l1f, whh_l1b, bhh_l1f, bhh_l1b, 1);
    // pooling + heads
    attn_head_kernel<<<BATCH, 256>>>(attn_w, attn_b, motor_w, motor_b,
                                     state_w, state_b, motor_k, out);
}

// round 5
// speedup vs baseline: 2.7599x; 1.1182x over previous
#include <cuda_runtime.h>
#include <cuda_bf16.h>
#include <math.h>

// Problem constants
#define BATCH 64
#define TT    1024
#define DIN   64
#define HID   128
#define G3    384   // 3*HID
#define D2    256   // 2*HID
#define MROWS (BATCH*TT)   // 65536

typedef unsigned long long ull;

// ---------------- f32x2 packed helpers (sm_103a FFMA2) ----------------------
__device__ __forceinline__ ull fma2(ull a, ull b, ull c) {
    ull d;
    asm("fma.rn.f32x2 %0, %1, %2, %3;" : "=l"(d) : "l"(a), "l"(b), "l"(c));
    return d;
}
__device__ __forceinline__ ull pack2(float lo, float hi) {
    ull d;
    asm("mov.b64 %0, {%1, %2};" : "=l"(d) : "f"(lo), "f"(hi));
    return d;
}
__device__ __forceinline__ float2 unpack2(ull v) {
    float2 r;
    asm("mov.b64 {%0, %1}, %2;" : "=f"(r.x), "=f"(r.y) : "l"(v));
    return r;
}
__device__ __forceinline__ float sigm(float x) {
    return 1.f / (1.f + __expf(-x));
}
__device__ __forceinline__ float ftanh(float x) {
    return __fmaf_rn(2.f, 1.f / (1.f + __expf(-2.f * x)), -1.f);
}

// ---------------- scratch (device globals; no allocation allowed) ----------
__device__ float g_xW[2][MROWS][G3];   // per-dir input projections (reused L0/L1)
__device__ float g_z0[MROWS][D2];      // layer-0 output [b*T+t][256]
__device__ float g_z1[MROWS][D2];      // layer-1 output

// ---------------- input projection GEMM: C = A @ W^T + bih (+bhh for r,z) --
__global__ __launch_bounds__(256)
void proj_gemm_kernel(const float* __restrict__ A0,
                      const float* __restrict__ Wf, const float* __restrict__ Wb,
                      const float* __restrict__ bf, const float* __restrict__ bb,
                      const float* __restrict__ bhf, const float* __restrict__ bhb,
                      int K, int layer)
{
    constexpr int BM = 128, BN = 64, BK = 16;
    __shared__ __align__(16) float As[BK][BM + 4];
    __shared__ __align__(16) float Ws[BK][BN + 4];

    const int dir = blockIdx.z;
    const float* __restrict__ A    = layer ? (const float*)g_z0 : A0;
    const float* __restrict__ Wp   = dir ? Wb : Wf;
    const float* __restrict__ bias = dir ? bb : bf;
    const float* __restrict__ bhh  = dir ? bhb : bhf;

    const int m0 = blockIdx.x * BM;
    const int n0 = blockIdx.y * BN;

    const int tid  = threadIdx.x;
    const int arow = tid >> 2;           // 0..63
    const int kq   = (tid & 3) * 4;      // 0,4,8,12
    const int tx   = tid & 15;           // N micro (4)
    const int ty   = tid >> 4;           // M micro (8 rows = 4 f32x2 pairs)

    ull acc2[4][4];
    #pragma unroll
    for (int i = 0; i < 4; ++i)
        #pragma unroll
        for (int j = 0; j < 4; ++j) acc2[i][j] = 0ull;

    for (int k0 = 0; k0 < K; k0 += BK) {
        {
            const float* p = A + (size_t)(m0 + arow) * K + k0 + kq;
            float4 v0 = *(const float4*)p;
            float4 v1 = *(const float4*)(p + (size_t)64 * K);
            As[kq + 0][arow] = v0.x; As[kq + 1][arow] = v0.y;
            As[kq + 2][arow] = v0.z; As[kq + 3][arow] = v0.w;
            As[kq + 0][arow + 64] = v1.x; As[kq + 1][arow + 64] = v1.y;
            As[kq + 2][arow + 64] = v1.z; As[kq + 3][arow + 64] = v1.w;
        }
        {
            const float* p = Wp + (size_t)(n0 + arow) * K + k0 + kq;
            float4 v = *(const float4*)p;
            Ws[kq + 0][arow] = v.x; Ws[kq + 1][arow] = v.y;
            Ws[kq + 2][arow] = v.z; Ws[kq + 3][arow] = v.w;
        }
        __syncthreads();

        #pragma unroll
        for (int kk = 0; kk < BK; ++kk) {
            ulonglong2 a01 = *(const ulonglong2*)&As[kk][ty * 8];
            ulonglong2 a23 = *(const ulonglong2*)&As[kk][ty * 8 + 4];
            float4 w4 = *(const float4*)&Ws[kk][tx * 4];
            ull am[4] = {a01.x, a01.y, a23.x, a23.y};
            ull wp[4] = {pack2(w4.x, w4.x), pack2(w4.y, w4.y),
                         pack2(w4.z, w4.z), pack2(w4.w, w4.w)};
            #pragma unroll
            for (int i = 0; i < 4; ++i)
                #pragma unroll
                for (int j = 0; j < 4; ++j)
                    acc2[i][j] = fma2(am[i], wp[j], acc2[i][j]);
        }
        __syncthreads();
    }

    float* Cout = &g_xW[dir][0][0];
    float4 b4 = *(const float4*)(bias + n0 + tx * 4);
    if (n0 < 2 * HID) {   // fold bhh into r,z gate biases (n-gate keeps bhh apart)
        float4 bh4 = *(const float4*)(bhh + n0 + tx * 4);
        b4.x += bh4.x; b4.y += bh4.y; b4.z += bh4.z; b4.w += bh4.w;
    }
    float* Crow = Cout + (size_t)(m0 + ty * 8) * G3 + n0 + tx * 4;
    #pragma unroll
    for (int i = 0; i < 4; ++i) {
        float2 c0 = unpack2(acc2[i][0]);
        float2 c1 = unpack2(acc2[i][1]);
        float2 c2 = unpack2(acc2[i][2]);
        float2 c3 = unpack2(acc2[i][3]);
        float4 lo = {c0.x + b4.x, c1.x + b4.y, c2.x + b4.z, c3.x + b4.w};
        float4 hi = {c0.y + b4.x, c1.y + b4.y, c2.y + b4.z, c3.y + b4.w};
        *(float4*)(Crow + (size_t)(2 * i)     * G3) = lo;
        *(float4*)(Crow + (size_t)(2 * i + 1) * G3) = hi;
    }
}

// ---------------- GRU recurrence -------------------------------------------
// 384 threads = rows (r:0-127, z:128-255, n:256-383).
// Each thread: 1 uniform gi load (own row), full Whh row in regs, pure dot.
// r,z threads apply their sigmoid BEFORE bar1 (overlapped, 8 warps) -> STS 256.
// n threads (warps 8-11, one per SMSP) do the short tail: tanh + blend.
__global__ __launch_bounds__(384, 1)
void gru_scan_kernel(const float* __restrict__ whh_f, const float* __restrict__ whh_b,
                     const float* __restrict__ bhh_f, const float* __restrict__ bhh_b,
                     int layer)
{
    const int b   = blockIdx.x >> 1;
    const int dir = blockIdx.x & 1;
    const int j   = threadIdx.x;                 // 0..383 = gate row

    const float* __restrict__ whh = dir ? whh_b : whh_f;
    const float* __restrict__ bhh = dir ? bhh_b : bhh_f;

    __shared__ __align__(16) float h_s[HID];
    __shared__ float rz_s[2 * HID];

    // load Whh row j into 64 packed f32x2 registers
    ull w2[64];
    #pragma unroll
    for (int i = 0; i < 64; i += 2) {
        ulonglong2 v = *(const ulonglong2*)(whh + (size_t)j * HID + 2 * i);
        w2[i] = v.x; w2[i + 1] = v.y;
    }
    const bool is_n = (j >= 2 * HID);
    const int  o    = j - 2 * HID;               // output index for n-threads
    const float bj  = is_n ? bhh[j] : 0.f;       // bhh_n stays inside r*(.)
    float hreg = 0.f;
    if (j < HID) h_s[j] = 0.f;

    const float* __restrict__ gi = &g_xW[dir][(size_t)b * TT][0];
    float* __restrict__ zout = (layer ? &g_z1[(size_t)b * TT][0]
                                      : &g_z0[(size_t)b * TT][0]) + dir * HID;

    // preload own-row gi for the first step
    const int t0 = dir ? (TT - 1) : 0;
    float gi_v = __ldcs(gi + (size_t)t0 * G3 + j);
    __syncthreads();

    for (int t = 0; t < TT; ++t) {
        const int tt = dir ? (TT - 1 - t) : t;

        // prefetch NEXT step's gi (covered by a full step of work)
        float pre = 0.f;
        if (t + 1 < TT) {
            const int tn = dir ? (TT - 2 - t) : (t + 1);
            pre = __ldcs(gi + (size_t)tn * G3 + j);
        }

        // gh = Whh[j,:] . h   (pure dot; 4-deep explicit LDS staging)
        ull a0 = 0ull, a1 = 0ull;
        const ull* h2 = (const ull*)h_s;
        #pragma unroll
        for (int i = 0; i < 64; i += 8) {
            ulonglong2 hv0 = *(const ulonglong2*)(h2 + i);
            ulonglong2 hv1 = *(const ulonglong2*)(h2 + i + 2);
            ulonglong2 hv2 = *(const ulonglong2*)(h2 + i + 4);
            ulonglong2 hv3 = *(const ulonglong2*)(h2 + i + 6);
            a0 = fma2(w2[i],     hv0.x, a0);
            a1 = fma2(w2[i + 1], hv0.y, a1);
            a0 = fma2(w2[i + 2], hv1.x, a0);
            a1 = fma2(w2[i + 3], hv1.y, a1);
            a0 = fma2(w2[i + 4], hv2.x, a0);
            a1 = fma2(w2[i + 5], hv2.y, a1);
            a0 = fma2(w2[i + 6], hv3.x, a0);
            a1 = fma2(w2[i + 7], hv3.y, a1);
        }
        float2 s0 = unpack2(a0), s1 = unpack2(a1);
        float gh = (s0.x + s0.y) + (s1.x + s1.y);

        // r,z threads: apply sigmoid here (parallel across 8 warps), publish
        if (!is_n) rz_s[j] = sigm(gi_v + gh);
        __syncthreads();

        // n threads: short tail = tanh + blend
        if (is_n) {
            float r  = rz_s[o];
            float zg = rz_s[HID + o];
            float n  = ftanh(gi_v + r * (gh + bj));
            hreg = (1.f - zg) * n + zg * hreg;
            h_s[o] = hreg;
            zout[(size_t)tt * D2 + o] = hreg;
        }
        gi_v = pre;
        __syncthreads();
    }
}

// ---------------- attention pooling + heads --------------------------------
__global__ __launch_bounds__(256)
void attn_head_kernel(const float* __restrict__ attn_w, const float* __restrict__ attn_b,
                      const float* __restrict__ motor_w, const float* __restrict__ motor_b,
                      const float* __restrict__ state_w, const float* __restrict__ state_b,
                      const int* __restrict__ motor_k, float* __restrict__ out)
{
    const int b = blockIdx.x;
    const int tid = threadIdx.x;       // 256 threads
    const int warp = tid >> 5, lane = tid & 31;

    __shared__ float sw[D2];
    __shared__ float sc[TT];
    __shared__ float red[256];
    __shared__ float pooled[D2];

    sw[tid] = attn_w[tid];
    __syncthreads();

    const float* __restrict__ zb = &g_z1[(size_t)b * TT][0];
    const float ab = attn_b[0];

    for (int t = warp; t < TT; t += 8) {
        const float* zt = zb + (size_t)t * D2;
        float s = 0.f;
        #pragma unroll
        for (int d = lane; d < D2; d += 32) s += zt[d] * sw[d];
        #pragma unroll
        for (int o = 16; o; o >>= 1) s += __shfl_xor_sync(0xffffffffu, s, o);
        if (lane == 0) sc[t] = s + ab;
    }
    __syncthreads();

    float m = -INFINITY;
    for (int t = tid; t < TT; t += 256) m = fmaxf(m, sc[t]);
    red[tid] = m; __syncthreads();
    for (int s = 128; s; s >>= 1) {
        if (tid < s) red[tid] = fmaxf(red[tid], red[tid + s]);
        __syncthreads();
    }
    m = red[0]; __syncthreads();

    float sum = 0.f;
    for (int t = tid; t < TT; t += 256) {
        float e = __expf(sc[t] - m);
        sc[t] = e;
        sum += e;
    }
    red[tid] = sum; __syncthreads();
    for (int s = 128; s; s >>= 1) {
        if (tid < s) red[tid] += red[tid + s];
        __syncthreads();
    }
    const float inv = 1.f / red[0];
    __syncthreads();

    float acc = 0.f;
    #pragma unroll 8
    for (int t = 0; t < TT; ++t) acc += sc[t] * zb[(size_t)t * D2 + tid];
    pooled[tid] = acc * inv;
    __syncthreads();

    if (warp < 7) {
        const float* wv;
        float bv;
        int mk = motor_k[b];
        if (warp < 5) { wv = motor_w + warp * D2;              bv = motor_b[warp]; }
        else          { int c = warp - 5;
                        wv = state_w + (size_t)(mk * 2 + c) * D2;
                        bv = state_b[mk * 2 + c]; }
        float s = 0.f;
        #pragma unroll
        for (int d = lane; d < D2; d += 32) s += pooled[d] * wv[d];
        #pragma unroll
        for (int o = 16; o; o >>= 1) s += __shfl_xor_sync(0xffffffffu, s, o);
        if (lane == 0) {
            if (warp < 5) out[b * 5 + warp] = s + bv;
            else          out[BATCH * 5 + b * 2 + (warp - 5)] = s + bv;
        }
    }
}

// ---------------- launch ----------------------------------------------------
extern "C" void kernel_launch(void* const* d_in, const int* in_sizes, int n_in,
                              void* d_out, int out_size)
{
    const float* x        = (const float*)d_in[0];
    const int*   motor_k  = (const int*)  d_in[1];
    const float* wih_l0f  = (const float*)d_in[2];
    const float* whh_l0f  = (const float*)d_in[3];
    const float* bih_l0f  = (const float*)d_in[4];
    const float* bhh_l0f  = (const float*)d_in[5];
    const float* wih_l0b  = (const float*)d_in[6];
    const float* whh_l0b  = (const float*)d_in[7];
    const float* bih_l0b  = (const float*)d_in[8];
    const float* bhh_l0b  = (const float*)d_in[9];
    const float* wih_l1f  = (const float*)d_in[10];
    const float* whh_l1f  = (const float*)d_in[11];
    const float* bih_l1f  = (const float*)d_in[12];
    const float* bhh_l1f  = (const float*)d_in[13];
    const float* wih_l1b  = (const float*)d_in[14];
    const float* whh_l1b  = (const float*)d_in[15];
    const float* bih_l1b  = (const float*)d_in[16];
    const float* bhh_l1b  = (const float*)d_in[17];
    const float* attn_w   = (const float*)d_in[18];
    const float* attn_b   = (const float*)d_in[19];
    const float* motor_w  = (const float*)d_in[20];
    const float* motor_b  = (const float*)d_in[21];
    const float* state_w  = (const float*)d_in[22];
    const float* state_b  = (const float*)d_in[23];
    float* out = (float*)d_out;

    dim3 gproj(MROWS / 128, G3 / 64, 2);

    // layer 0
    proj_gemm_kernel<<<gproj, 256>>>(x, wih_l0f, wih_l0b, bih_l0f, bih_l0b,
                                     bhh_l0f, bhh_l0b, DIN, 0);
    gru_scan_kernel<<<BATCH * 2, 384>>>(whh_l0f, whh_l0b, bhh_l0f, bhh_l0b, 0);
    // layer 1
    proj_gemm_kernel<<<gproj, 256>>>(nullptr, wih_l1f, wih_l1b, bih_l1f, bih_l1b,
                                     bhh_l1f, bhh_l1b, D2, 1);
    gru_scan_kernel<<<BATCH * 2, 384>>>(whh_l1f, whh_l1b, bhh_l1f, bhh_l1b, 1);
    // pooling + heads
    attn_head_kernel<<<BATCH, 256>>>(attn_w, attn_b, motor_w, motor_b,
                                     state_w, state_b, motor_k, out);
}